// round 6
// baseline (speedup 1.0000x reference)
#include <cuda_runtime.h>
#include <math.h>
#include <stdint.h>

#define NPRED_TOTAL 259584      // 32 * 8112
#define NP0         8112        // predictions in batch 0 (3*52*52)
#define HW_         2704        // 52*52
#define ATTRS       85
#define OUT_ELEMS   22064640    // 32*8112*85
#define MAXDET      100
#define NCLS        80
#define CAND_MAX    6144        // >> observed ~3650 candidates
#define CLS_CAP     2048        // per-class candidate cap (expected ~46)
#define KEPT_MAX    CAND_MAX

// ---- device scratch ----
__device__ float4   g_obox[NP0];
__device__ float4   g_corners[NP0];
__device__ float    g_conf[NP0];
__device__ float    g_clsconf[NP0];
__device__ float    g_clspred[NP0];
__device__ uint64_t g_ckeys[CAND_MAX];   // key = score_inv:32 | cls:7 | idx:13
__device__ uint64_t g_kept[KEPT_MAX];    // kept candidate keys (all classes)
__device__ int      g_count;             // candidates (zero-init; reset each launch)
__device__ int      g_kcount;            // kept count
__device__ int      g_done;              // finished-block ticket

__device__ __forceinline__ float sigf(float x) { return 1.0f / (1.0f + expf(-x)); }

// ---------------------------------------------------------------------------
// Decode (identical math to R5; only the key layout changed to carry cls).
// ---------------------------------------------------------------------------
__global__ __launch_bounds__(256) void decode_kernel(
    const float* __restrict__ in,
    const float* __restrict__ anchors,
    float* __restrict__ out)
{
    __shared__ float sm[64 * ATTRS];
    const int tx = threadIdx.x;
    const int q  = tx >> 6;
    const int lp = tx & 63;
    const int n  = blockIdx.x * 64 + lp;
    const int b  = n / NP0;
    const int r  = n - b * NP0;
    const int a  = r / HW_;
    const int hw = r - a * HW_;
    const int gy = hw / 52;
    const int gx = hw - gy * 52;

    const float* p = in + ((long)(b * 255 + a * 85)) * HW_ + hw;
    float* row = sm + lp * ATTRS;

    float t[22];
    #pragma unroll
    for (int k = 0; k < 22; k++) {
        int e = q + 4 * k;
        if (e < ATTRS) t[k] = p[(long)e * HW_];
    }

    if (q == 0) {
        row[0] = (sigf(t[0]) + (float)gx) / 52.0f;
        row[4] = sigf(t[1]);
        #pragma unroll
        for (int k = 2; k < 22; k++) row[4 * k] = sigf(t[k]);
    } else if (q == 1) {
        row[1] = (sigf(t[0]) + (float)gy) / 52.0f;
        #pragma unroll
        for (int k = 1; k < 21; k++) row[1 + 4 * k] = sigf(t[k]);
    } else if (q == 2) {
        float aw = anchors[(6 + a) * 2 + 0] * 0.125f;
        row[2] = (expf(t[0]) * aw) / 52.0f;
        #pragma unroll
        for (int k = 1; k < 21; k++) row[2 + 4 * k] = sigf(t[k]);
    } else {
        float ah = anchors[(6 + a) * 2 + 1] * 0.125f;
        row[3] = (expf(t[0]) * ah) / 52.0f;
        #pragma unroll
        for (int k = 1; k < 21; k++) row[3 + 4 * k] = sigf(t[k]);
    }
    __syncthreads();

    {
        const float4* sm4 = (const float4*)sm;
        float4* ob4 = (float4*)(out + (long)blockIdx.x * (64 * ATTRS));
        #pragma unroll 6
        for (int i = tx; i < (64 * ATTRS) / 4; i += 256) ob4[i] = sm4[i];
    }

    if (tx < 64) {
        bool valid = false; uint64_t key = 0;
        if (n < NP0) {
            float conf = row[4];
            float cc = row[5]; int cp = 0;
            #pragma unroll 16
            for (int c = 1; c < NCLS; c++) {
                float v = row[5 + c];
                if (v > cc) { cc = v; cp = c; }   // strict > : lowest idx on ties
            }
            float score = conf * cc;
            if (score >= 0.5f) {
                valid = true;
                float bx = row[0], by = row[1], bw = row[2], bh = row[3];
                float hx = bw * 0.5f, hy = bh * 0.5f;
                float x1 = bx - hx, y1 = by - hy, x2 = bx + hx, y2 = by + hy;
                float off = (float)cp * 4096.0f;
                g_corners[n] = make_float4(x1, y1, x2, y2);
                g_obox[n]    = make_float4(x1 + off, y1 + off, x2 + off, y2 + off);
                g_conf[n]    = conf;
                g_clsconf[n] = cc;
                g_clspred[n] = (float)cp;
                key = ((uint64_t)(__float_as_uint(score) ^ 0xFFFFFFFFu) << 20)
                    | ((uint64_t)(unsigned)cp << 13) | (unsigned)n;
            }
        }
        unsigned m = __ballot_sync(0xffffffffu, valid);
        int base = 0;
        if ((tx & 31) == 0 && m) base = atomicAdd(&g_count, __popc(m));
        base = __shfl_sync(0xffffffffu, base, 0);
        if (valid) {
            int pos = base + __popc(m & ((1u << (tx & 31)) - 1u));
            if (pos < CAND_MAX) g_ckeys[pos] = key;
        }
    }
}

// ---------------------------------------------------------------------------
// Fused NMS: 80 blocks (one per class), 1024 threads.
//  A) filter own-class keys from g_ckeys -> smem (value-based => deterministic)
//  B) local rank sort (keys unique => exact permutation)
//  C) warp-0 greedy sweep over smem-resident boxes (cap 100/class is exact:
//     a candidate behind 100 higher-scored same-class keeps can never reach
//     the global top-100; cross-class IoU is exactly 0 due to 4096 offsets)
//  D) append kept keys to global list; LAST block rank-selects the 100
//     smallest keys (global score-desc order), writes det, resets counters.
// ---------------------------------------------------------------------------
__global__ __launch_bounds__(1024) void nms_kernel(float* __restrict__ out)
{
    extern __shared__ char dsm[];              // 48KB dynamic, phase-reused
    uint64_t* dkeys = (uint64_t*)dsm;          // A: raw class keys  (<= CLS_CAP)
    float4*   dbox  = (float4*)dsm;            // C: sorted boxes    (<= CLS_CAP)
    uint64_t* dkept = (uint64_t*)dsm;          // E: kept keys       (<= KEPT_MAX)

    __shared__ uint64_t s_sorted[CLS_CAP];
    __shared__ float4 s_k[MAXDET];
    __shared__ float  s_ka[MAXDET];
    __shared__ int    s_kidx[MAXDET];
    __shared__ int    s_ord[MAXDET];
    __shared__ int    s_nc, s_nk, s_gbase, s_ticket, s_np;

    const int tid = threadIdx.x;
    const int c   = blockIdx.x;
    int M = g_count; if (M > CAND_MAX) M = CAND_MAX;

    if (tid == 0) s_nc = 0;
    __syncthreads();

    // A: filter this class
    for (int i = tid; i < M; i += 1024) {
        uint64_t k = g_ckeys[i];
        if ((int)((k >> 13) & 0x7Fu) == c) {
            int pos = atomicAdd(&s_nc, 1);
            if (pos < CLS_CAP) dkeys[pos] = k;
        }
    }
    __syncthreads();
    int nc = s_nc; if (nc > CLS_CAP) nc = CLS_CAP;

    // B: rank sort into s_sorted (ascending key = score desc, idx asc)
    {
        uint64_t own[2]; int rk[2];
        #pragma unroll
        for (int s = 0; s < 2; s++) {
            int i = tid + (s << 10);
            if (i < nc) {
                uint64_t my = dkeys[i];
                int r2 = 0;
                for (int j = 0; j < nc; j++) r2 += (dkeys[j] < my) ? 1 : 0;
                own[s] = my; rk[s] = r2;
            } else rk[s] = -1;
        }
        __syncthreads();
        #pragma unroll
        for (int s = 0; s < 2; s++)
            if (rk[s] >= 0) s_sorted[rk[s]] = own[s];
    }
    __syncthreads();

    // C-prep: boxes into dynamic smem (overwrites dkeys; sorted copy is safe)
    for (int i = tid; i < nc; i += 1024) {
        int orig = (int)(s_sorted[i] & 0x1FFFu);
        dbox[i] = g_obox[orig];
    }
    __syncthreads();

    // C: warp-0 greedy sweep, lane-parallel over kept
    if (tid < 32) {
        const int lane = tid;
        int nk = 0;
        for (int i = 0; i < nc && nk < MAXDET; i++) {
            float4 B = dbox[i];                       // smem broadcast
            float aC = (B.z - B.x) * (B.w - B.y);
            bool sup = false;
            #pragma unroll
            for (int t = 0; t < 4; t++) {
                int idx = lane + (t << 5);
                if (idx < nk) {
                    float4 K = s_k[idx];
                    float ltx = fmaxf(K.x, B.x), lty = fmaxf(K.y, B.y);
                    float rbx = fminf(K.z, B.z), rby = fminf(K.w, B.w);
                    float iw = fmaxf(rbx - ltx, 0.0f), ih = fmaxf(rby - lty, 0.0f);
                    float inter = iw * ih;
                    float den = s_ka[idx] + aC - inter + 1e-9f;  // exact ref expr
                    if (inter / den > 0.4f) sup = true;
                }
            }
            if (__ballot_sync(0xffffffffu, sup) == 0u) {
                if (lane == 0) { s_k[nk] = B; s_ka[nk] = aC; s_kidx[nk] = i; }
                nk++;
                __syncwarp();
            }
        }
        if (lane == 0) s_nk = nk;
    }
    __syncthreads();

    // D: append kept keys to the global kept list
    int nk = s_nk;
    if (tid == 0) s_gbase = (nk > 0) ? atomicAdd(&g_kcount, nk) : 0;
    __syncthreads();
    for (int t = tid; t < nk; t += 1024) {
        int gp = s_gbase + t;
        if (gp < KEPT_MAX) g_kept[gp] = s_sorted[s_kidx[t]];
    }

    __threadfence();
    if (tid == 0) s_ticket = atomicAdd(&g_done, 1);
    __syncthreads();
    if (s_ticket != NCLS - 1) return;

    // ===== last block: global top-100 among kept =====
    __threadfence();
    int K = g_kcount; if (K > KEPT_MAX) K = KEPT_MAX;
    for (int i = tid; i < K; i += 1024) dkept[i] = g_kept[i];
    __syncthreads();

    if (tid == 0) s_np = (K < MAXDET) ? K : MAXDET;
    for (int i = tid; i < K; i += 1024) {
        uint64_t my = dkept[i];
        int rk = 0;
        for (int j = 0; j < K; j++) rk += (dkept[j] < my) ? 1 : 0;
        if (rk < MAXDET) s_ord[rk] = (int)(my & 0x1FFFu);
    }
    __syncthreads();

    int np = s_np;
    if (tid < MAXDET) {
        float* d = out + (long)OUT_ELEMS + tid * 7;
        if (tid < np) {
            int orig = s_ord[tid];
            float4 c4 = g_corners[orig];
            d[0] = c4.y * 416.0f;
            d[1] = c4.x * 416.0f;
            d[2] = c4.w * 416.0f;
            d[3] = c4.z * 416.0f;
            d[4] = g_conf[orig];
            d[5] = g_clsconf[orig];
            d[6] = g_clspred[orig];
        } else {
            #pragma unroll
            for (int e = 0; e < 7; e++) d[e] = 0.0f;
        }
    }

    // reset for next graph replay
    if (tid == 0) { g_count = 0; g_kcount = 0; g_done = 0; }
}

extern "C" void kernel_launch(void* const* d_in, const int* in_sizes, int n_in,
                              void* d_out, int out_size)
{
    const float* in      = (const float*)d_in[0];
    const float* anchors = (const float*)d_in[1];
    float* out = (float*)d_out;

    static int attr_set = 0;
    if (!attr_set) {
        cudaFuncSetAttribute(nms_kernel, cudaFuncAttributeMaxDynamicSharedMemorySize,
                             KEPT_MAX * (int)sizeof(uint64_t));
        attr_set = 1;
    }

    decode_kernel<<<NPRED_TOTAL / 64, 256>>>(in, anchors, out);
    nms_kernel<<<NCLS, 1024, KEPT_MAX * sizeof(uint64_t)>>>(out);
}